// round 16
// baseline (speedup 1.0000x reference)
#include <cuda_runtime.h>
#include <cuda_fp16.h>

#define BB 4
#define NN 4096
#define DD 16
#define CC 128
#define LOG2E 1.4426950408889634f
#define NT 32

typedef unsigned long long ull;

__device__ __align__(16) float g_Q[BB * NN * DD];
__device__ __align__(16) __half g_Kh[BB * NN * DD];  // fp16 K, pre-scaled by log2(e)
__device__ __align__(16) float g_V[BB * NN * DD];    // after vfold: u = colinv * v
__device__ __align__(16) __half g_E[(size_t)BB * NN * NN];  // exp(e), N-MAJOR: [b][n][m]
__device__ float g_rowinv[BB * NN];
__device__ float g_cpart[8 * BB * NN];               // colsum partials per n-chunk
__device__ float g_T[BB * DD * NN];
__device__ float g_part[BB * NT * 8];

__device__ __forceinline__ ull pack2(float lo, float hi) {
    ull r; asm("mov.b64 %0, {%1, %2};" : "=l"(r) : "f"(lo), "f"(hi)); return r;
}
__device__ __forceinline__ ull fma2(ull a, ull b, ull c) {
    ull d; asm("fma.rn.f32x2 %0, %1, %2, %3;" : "=l"(d) : "l"(a), "l"(b), "l"(c)); return d;
}
__device__ __forceinline__ ull add2(ull a, ull b) {
    ull d; asm("add.rn.f32x2 %0, %1, %2;" : "=l"(d) : "l"(a), "l"(b)); return d;
}
__device__ __forceinline__ float ex2(float x) {
    float y; asm("ex2.approx.ftz.f32 %0, %1;" : "=f"(y) : "f"(x)); return y;
}
__device__ __forceinline__ unsigned h2u(__half2 h) {
    union { __half2 h; unsigned u; } cv; cv.h = h; return cv.u;
}
__device__ __forceinline__ void cpa16(unsigned dst, const void* src) {
    asm volatile("cp.async.ca.shared.global [%0], [%1], 16;" :: "r"(dst), "l"(src));
}
__device__ __forceinline__ void cp_commit() { asm volatile("cp.async.commit_group;"); }
template <int N> __device__ __forceinline__ void cp_wait() {
    asm volatile("cp.async.wait_group %0;" :: "n"(N));
}
__device__ __forceinline__ void ldk(ull* kk, const float* p) {
    const ulonglong2* k2 = (const ulonglong2*)p;
#pragma unroll
    for (int i = 0; i < 4; i++) { ulonglong2 t = k2[i]; kk[2 * i] = t.x; kk[2 * i + 1] = t.y; }
}

// mma.sync m16n8k16 row.col f32 = f16*f16 + f32
__device__ __forceinline__ void mma16816(float& d0, float& d1, float& d2, float& d3,
                                         unsigned a0, unsigned a1, unsigned a2, unsigned a3,
                                         unsigned b0, unsigned b1) {
    asm volatile(
        "mma.sync.aligned.m16n8k16.row.col.f32.f16.f16.f32 "
        "{%0,%1,%2,%3}, {%4,%5,%6,%7}, {%8,%9}, {%10,%11,%12,%13};"
        : "=f"(d0), "=f"(d1), "=f"(d2), "=f"(d3)
        : "r"(a0), "r"(a1), "r"(a2), "r"(a3), "r"(b0), "r"(b1),
          "f"(0.f), "f"(0.f), "f"(0.f), "f"(0.f));
}

// ---------------------------------------------------------------------------
// Kernel 1: projections. Q fp32; K fp16 pre-scaled by log2(e); V fp32.
// ---------------------------------------------------------------------------
__global__ void proj_kernel(const float* __restrict__ x_q, const float* __restrict__ x_kv,
                            const float* __restrict__ xyz_q, const float* __restrict__ xyz_kv,
                            const float* __restrict__ w_qk, const float* __restrict__ w_v,
                            const float* __restrict__ b_v,
                            const float* __restrict__ w_pos_q, const float* __restrict__ w_pos_kv) {
    __shared__ __align__(16) float s_wqk[CC][DD];
    __shared__ __align__(16) float s_wv[CC][DD];
    const int b = blockIdx.z;
    const int isKV = blockIdx.y;
    const int n = blockIdx.x * 128 + threadIdx.x;
    for (int i = threadIdx.x; i < CC * DD; i += 128) {
        int d = i / CC, c = i % CC;
        s_wqk[c][d] = w_qk[i];
        s_wv[c][d] = w_v[i];
    }
    __syncthreads();
    if (isKV == 0) {
        float p0 = xyz_q[(b * 3 + 0) * NN + n];
        float p1 = xyz_q[(b * 3 + 1) * NN + n];
        float p2 = xyz_q[(b * 3 + 2) * NN + n];
        float acc[DD];
#pragma unroll
        for (int d = 0; d < DD; d++)
            acc[d] = w_pos_q[d * 3] * p0 + w_pos_q[d * 3 + 1] * p1 + w_pos_q[d * 3 + 2] * p2;
        const float* xp = x_q + (size_t)b * CC * NN + n;
#pragma unroll 4
        for (int c = 0; c < CC; c++) {
            float xv = xp[(size_t)c * NN];
            const float4* w4 = (const float4*)s_wqk[c];
#pragma unroll
            for (int i = 0; i < 4; i++) {
                float4 w = w4[i];
                acc[4 * i + 0] += w.x * xv; acc[4 * i + 1] += w.y * xv;
                acc[4 * i + 2] += w.z * xv; acc[4 * i + 3] += w.w * xv;
            }
        }
        float4* qp = (float4*)(g_Q + ((size_t)(b * NN + n)) * DD);
#pragma unroll
        for (int i = 0; i < 4; i++)
            qp[i] = make_float4(acc[4 * i], acc[4 * i + 1], acc[4 * i + 2], acc[4 * i + 3]);
    } else {
        float p0 = xyz_kv[(b * 3 + 0) * NN + n];
        float p1 = xyz_kv[(b * 3 + 1) * NN + n];
        float p2 = xyz_kv[(b * 3 + 2) * NN + n];
        float ak[DD], av[DD];
#pragma unroll
        for (int d = 0; d < DD; d++) {
            float pos = w_pos_kv[d * 3] * p0 + w_pos_kv[d * 3 + 1] * p1 + w_pos_kv[d * 3 + 2] * p2;
            ak[d] = pos;
            av[d] = pos + b_v[d];
        }
        const float* xp = x_kv + (size_t)b * CC * NN + n;
#pragma unroll 2
        for (int c = 0; c < CC; c++) {
            float xv = xp[(size_t)c * NN];
            const float4* wq4 = (const float4*)s_wqk[c];
            const float4* wv4 = (const float4*)s_wv[c];
#pragma unroll
            for (int i = 0; i < 4; i++) {
                float4 wq = wq4[i], wv = wv4[i];
                ak[4 * i + 0] += wq.x * xv; ak[4 * i + 1] += wq.y * xv;
                ak[4 * i + 2] += wq.z * xv; ak[4 * i + 3] += wq.w * xv;
                av[4 * i + 0] += wv.x * xv; av[4 * i + 1] += wv.y * xv;
                av[4 * i + 2] += wv.z * xv; av[4 * i + 3] += wv.w * xv;
            }
        }
        union { __half2 h[8]; uint4 u[2]; } kh;
#pragma unroll
        for (int i = 0; i < 8; i++)
            kh.h[i] = __floats2half2_rn(ak[2 * i] * LOG2E, ak[2 * i + 1] * LOG2E);
        uint4* kp = (uint4*)(g_Kh + ((size_t)(b * NN + n)) * DD);
        kp[0] = kh.u[0];
        kp[1] = kh.u[1];
        float4* vp = (float4*)(g_V + ((size_t)(b * NN + n)) * DD);
#pragma unroll
        for (int i = 0; i < 4; i++)
            vp[i] = make_float4(av[4 * i], av[4 * i + 1], av[4 * i + 2], av[4 * i + 3]);
    }
}

// ---------------------------------------------------------------------------
// Kernel 2: rowsum via HMMA, E stored n-major — no smem, no barriers.
// Warp w owns n-rows [w*16, w*16+16). Fragments write half2 straight to E.
// ---------------------------------------------------------------------------
__global__ __launch_bounds__(256, 1) void rowsum_kernel() {
    const int tid = threadIdx.x, lane = tid & 31, w = tid >> 5;
    const int g = lane >> 2, t = lane & 3;
    const int b = blockIdx.y;
    const int nbase = blockIdx.x * 128 + w * 16;

    // A fragment: Q rows nbase+g, nbase+g+8 (fp32 -> fp16)
    unsigned a0, a1, a2, a3;
    {
        const float2* q0 = (const float2*)(g_Q + ((size_t)(b * NN + nbase + g)) * DD);
        const float2* q1 = (const float2*)(g_Q + ((size_t)(b * NN + nbase + g + 8)) * DD);
        float2 r00 = q0[t], r02 = q0[t + 4];
        float2 r10 = q1[t], r12 = q1[t + 4];
        a0 = h2u(__floats2half2_rn(r00.x, r00.y));
        a2 = h2u(__floats2half2_rn(r02.x, r02.y));
        a1 = h2u(__floats2half2_rn(r10.x, r10.y));
        a3 = h2u(__floats2half2_rn(r12.x, r12.y));
    }

    const __half* kbase = g_Kh + (size_t)b * NN * DD;
    __half* erow0 = g_E + ((size_t)(b * NN + nbase + g)) * NN;
    __half* erow1 = erow0 + (size_t)8 * NN;
    float accA = 0.f, accB = 0.f;

#pragma unroll 2
    for (int mt = 0; mt < 512; ++mt) {
        const int m0 = mt * 8;
        const __half* kr = kbase + (size_t)(m0 + g) * DD;
        unsigned b0 = *(const unsigned*)(kr + 2 * t);
        unsigned b1 = *(const unsigned*)(kr + 2 * t + 8);
        float d0, d1, d2, d3;
        mma16816(d0, d1, d2, d3, a0, a1, a2, a3, b0, b1);
        float e0 = ex2(d0), e1 = ex2(d1), e2 = ex2(d2), e3 = ex2(d3);
        accA += e0 + e1;
        accB += e2 + e3;
        *(__half2*)(erow0 + m0 + 2 * t) = __floats2half2_rn(e0, e1);
        *(__half2*)(erow1 + m0 + 2 * t) = __floats2half2_rn(e2, e3);
    }

    accA += __shfl_xor_sync(0xffffffffu, accA, 1);
    accA += __shfl_xor_sync(0xffffffffu, accA, 2);
    accB += __shfl_xor_sync(0xffffffffu, accB, 1);
    accB += __shfl_xor_sync(0xffffffffu, accB, 2);
    if (t == 0) {
        g_rowinv[b * NN + nbase + g] = 1.0f / accA;
        g_rowinv[b * NN + nbase + g + 8] = 1.0f / accB;
    }
}

// ---------------------------------------------------------------------------
// Kernel 3: colsum partials over n-chunks of 512. Coalesced E rows.
// ---------------------------------------------------------------------------
__global__ __launch_bounds__(256, 2) void colsum_kernel() {
    __shared__ float sri[512];
    const int tid = threadIdx.x;
    const int b = blockIdx.y;
    const int mchunk = blockIdx.x & 3, nchunk = blockIdx.x >> 2;
    const int mbase = mchunk * 1024, nbase = nchunk * 512;

    for (int i = tid; i < 512; i += 256) sri[i] = g_rowinv[b * NN + nbase + i];
    __syncthreads();

    const __half* ebase = g_E + ((size_t)(b * NN + nbase)) * NN + mbase + tid * 4;
    float a0 = 0.f, a1 = 0.f, a2 = 0.f, a3 = 0.f;
#pragma unroll 1
    for (int n = 0; n < 512; n += 8) {
        uint2 r[8];
#pragma unroll
        for (int j = 0; j < 8; j++)
            r[j] = *(const uint2*)(ebase + (size_t)(n + j) * NN);
#pragma unroll
        for (int j = 0; j < 8; j++) {
            const __half2* h = (const __half2*)&r[j];
            float2 f0 = __half22float2(h[0]);
            float2 f1 = __half22float2(h[1]);
            float ri = sri[n + j];
            a0 += f0.x * ri; a1 += f0.y * ri;
            a2 += f1.x * ri; a3 += f1.y * ri;
        }
    }
    float4* dst = (float4*)(g_cpart + ((size_t)(nchunk * BB + b)) * NN + mbase + tid * 4);
    *dst = make_float4(a0, a1, a2, a3);
}

// ---------------------------------------------------------------------------
// Kernel 3b: fold colsum partials, scale V in place (u = colinv * v).
// ---------------------------------------------------------------------------
__global__ void vfold_kernel() {
    const int b = blockIdx.y;
    const int m = blockIdx.x * 256 + threadIdx.x;
    float s = 0.f;
#pragma unroll
    for (int c = 0; c < 8; c++) s += g_cpart[((size_t)(c * BB + b)) * NN + m];
    float ci = 1.0f / (1e-9f + s);
    float4* vp = (float4*)(g_V + ((size_t)(b * NN + m)) * DD);
#pragma unroll
    for (int i = 0; i < 4; i++) {
        float4 v = vp[i];
        vp[i] = make_float4(v.x * ci, v.y * ci, v.z * ci, v.w * ci);
    }
}

// ---------------------------------------------------------------------------
// Kernel 4: AV sweep. E n-major: per lane-row per 16-m tile = 2x LDG.128.
// u (=ci*v) via cp.async double-buffer.
// ---------------------------------------------------------------------------
__global__ __launch_bounds__(256, 1) void pass3_kernel(const float* __restrict__ w_t,
                                                       const float* __restrict__ b_t) {
    __shared__ __align__(16) float sbig[8192];
    __shared__ float swt[256];
    __shared__ float sred[1024];
    const int tid = threadIdx.x, lane = tid & 31, w = tid >> 5;
    const int b = blockIdx.y;
    const int n0blk = blockIdx.x * 128;

    swt[tid] = w_t[tid];

    const char* vbase = (const char*)(g_V + ((size_t)b * NN + (size_t)w * 512) * DD);
    const __half* er[4];
#pragma unroll
    for (int r = 0; r < 4; r++)
        er[r] = g_E + ((size_t)(b * NN + n0blk + lane * 4 + r)) * NN + w * 512;
    float* svw = sbig + w * 512;
    unsigned vb[2] = {(unsigned)__cvta_generic_to_shared(svw),
                      (unsigned)__cvta_generic_to_shared(svw + 256)};

    ull xr[32];
#pragma unroll
    for (int i = 0; i < 32; i++) xr[i] = 0ULL;

    auto issue = [&](int it, int buf) {
        const char* vsrc = vbase + (size_t)it * 1024;
        cpa16(vb[buf] + lane * 16, vsrc + lane * 16);
        cpa16(vb[buf] + 512 + lane * 16, vsrc + 512 + lane * 16);
        cp_commit();
    };
    // 16 m-halves per lane-row per tile = 2 uint4 per row
    auto ld_eh = [&](uint4* eh, int it) {
#pragma unroll
        for (int r = 0; r < 4; r++) {
            eh[2 * r]     = *(const uint4*)(er[r] + it * 16);
            eh[2 * r + 1] = *(const uint4*)(er[r] + it * 16 + 8);
        }
    };
    auto compute = [&](const uint4* eh, int buf) {
        const float* vs = svw + buf * 256;
        const __half2* h0 = (const __half2*)&eh[0];   // 8 half2 = 16 m values
        const __half2* h1 = (const __half2*)&eh[2];
        const __half2* h2 = (const __half2*)&eh[4];
        const __half2* h3 = (const __half2*)&eh[6];
#pragma unroll
        for (int mm = 0; mm < 16; ++mm) {
            ull vv[8];
            ldk(vv, vs + mm * DD);
            float f0 = (mm & 1) ? __high2float(h0[mm >> 1]) : __low2float(h0[mm >> 1]);
            float f1 = (mm & 1) ? __high2float(h1[mm >> 1]) : __low2float(h1[mm >> 1]);
            float f2 = (mm & 1) ? __high2float(h2[mm >> 1]) : __low2float(h2[mm >> 1]);
            float f3 = (mm & 1) ? __high2float(h3[mm >> 1]) : __low2float(h3[mm >> 1]);
            ull w0 = pack2(f0, f0), w1 = pack2(f1, f1);
            ull w2 = pack2(f2, f2), w3 = pack2(f3, f3);
#pragma unroll
            for (int i = 0; i < 8; i++) {
                xr[i]      = fma2(w0, vv[i], xr[i]);
                xr[8 + i]  = fma2(w1, vv[i], xr[8 + i]);
                xr[16 + i] = fma2(w2, vv[i], xr[16 + i]);
                xr[24 + i] = fma2(w3, vv[i], xr[24 + i]);
            }
        }
    };

    uint4 ehA[8], ehB[8];
    issue(0, 0);
    issue(1, 1);
    ld_eh(ehA, 0);
    cp_wait<1>();
    __syncwarp();

#pragma unroll 1
    for (int it = 0; it < 32; it += 2) {
        ld_eh(ehB, it + 1);
        compute(ehA, 0);
        __syncwarp();
        if (it + 2 < 32) { issue(it + 2, 0); cp_wait<1>(); } else { cp_wait<0>(); }
        __syncwarp();
        if (it + 2 < 32) ld_eh(ehA, it + 2);
        compute(ehB, 1);
        __syncwarp();
        if (it + 3 < 32) { issue(it + 3, 1); cp_wait<1>(); } else { cp_wait<0>(); }
        __syncwarp();
    }

    __syncthreads();
    if (w >= 4) {
        ull* d = (ull*)(sbig + ((size_t)(w - 4) * 128 + lane * 4) * DD);
#pragma unroll
        for (int i = 0; i < 32; i++) d[i] = xr[i];
    }
    __syncthreads();
    if (w < 4) {
        ull* d = (ull*)(sbig + ((size_t)w * 128 + lane * 4) * DD);
#pragma unroll
        for (int i = 0; i < 32; i++) d[i] = add2(d[i], xr[i]);
    }
    __syncthreads();

    if (tid < 128) {
        const int row = n0blk + tid;
        float rinv = g_rowinv[b * NN + row];
        float xrf[DD];
        const float* s0 = sbig + tid * DD;
#pragma unroll
        for (int d = 0; d < DD; d++)
            xrf[d] = (s0[d] + s0[2048 + d] + s0[4096 + d] + s0[6144 + d]) * rinv;
        const float* qg = g_Q + ((size_t)(b * NN + row)) * DD;
        float diff[DD];
#pragma unroll
        for (int d = 0; d < DD; d++) diff[d] = qg[d] - xrf[d];
        float gs[4] = {0.f, 0.f, 0.f, 0.f}, gs2[4] = {0.f, 0.f, 0.f, 0.f};
#pragma unroll
        for (int o = 0; o < DD; o++) {
            float s = b_t[o];
#pragma unroll
            for (int d = 0; d < DD; d++) s += swt[o * DD + d] * diff[d];
            g_T[((size_t)(b * DD + o)) * NN + row] = s;
            gs[o >> 2] += s;
            gs2[o >> 2] += s * s;
        }
#pragma unroll
        for (int g = 0; g < 4; g++) {
            sred[tid * 8 + g] = gs[g];
            sred[tid * 8 + 4 + g] = gs2[g];
        }
    }
    __syncthreads();
    for (int s = 64; s > 0; s >>= 1) {
        if (tid < s) {
#pragma unroll
            for (int j = 0; j < 8; j++) sred[tid * 8 + j] += sred[(tid + s) * 8 + j];
        }
        __syncthreads();
    }
    if (tid < 8) g_part[((size_t)(b * NT + blockIdx.x)) * 8 + tid] = sred[tid];
}

// ---------------------------------------------------------------------------
// Kernel 5: finalize GN stats, relu, + q^T.
// ---------------------------------------------------------------------------
__global__ void final_kernel(const float* __restrict__ gamma, const float* __restrict__ beta,
                             float* __restrict__ out) {
    __shared__ float sq[128 * 17];
    __shared__ float ssc[DD], ssh[DD];
    const int b = blockIdx.y;
    const int tid = threadIdx.x;
    const int n0 = blockIdx.x * 128;
    if (tid < DD) {
        int g = tid >> 2;
        float s = 0.f, s2 = 0.f;
        for (int t = 0; t < NT; t++) {
            s += g_part[(b * NT + t) * 8 + g];
            s2 += g_part[(b * NT + t) * 8 + 4 + g];
        }
        float cnt = (float)(4 * NN);
        float mean = s / cnt;
        float var = s2 / cnt - mean * mean;
        float inv = rsqrtf(var + 1e-5f);
        float sc = gamma[tid] * inv;
        ssc[tid] = sc;
        ssh[tid] = beta[tid] - mean * sc;
    }
    const float* qsrc = g_Q + ((size_t)(b * NN + n0)) * DD;
    for (int i = tid; i < 128 * DD; i += 256) sq[(i >> 4) * 17 + (i & 15)] = qsrc[i];
    __syncthreads();
    for (int i = tid; i < 128 * DD; i += 256) {
        int c = i >> 7, j = i & 127;
        size_t idx = ((size_t)(b * DD + c)) * NN + n0 + j;
        float tv = g_T[idx];
        float r = fmaxf(tv * ssc[c] + ssh[c], 0.f);
        out[idx] = r + sq[j * 17 + c];
    }
}

extern "C" void kernel_launch(void* const* d_in, const int* in_sizes, int n_in,
                              void* d_out, int out_size) {
    const float* x_q      = (const float*)d_in[0];
    const float* x_kv     = (const float*)d_in[1];
    const float* xyz_q    = (const float*)d_in[2];
    const float* xyz_kv   = (const float*)d_in[3];
    const float* w_qk     = (const float*)d_in[4];
    const float* w_v      = (const float*)d_in[5];
    const float* b_v      = (const float*)d_in[6];
    const float* w_t      = (const float*)d_in[7];
    const float* b_t      = (const float*)d_in[8];
    const float* gamma    = (const float*)d_in[9];
    const float* beta     = (const float*)d_in[10];
    const float* w_pos_q  = (const float*)d_in[11];
    const float* w_pos_kv = (const float*)d_in[12];
    float* out = (float*)d_out;

    proj_kernel<<<dim3(32, 2, BB), 128>>>(x_q, x_kv, xyz_q, xyz_kv, w_qk, w_v, b_v,
                                          w_pos_q, w_pos_kv);
    rowsum_kernel<<<dim3(32, BB), 256>>>();
    colsum_kernel<<<dim3(32, BB), 256>>>();
    vfold_kernel<<<dim3(16, BB), 256>>>();
    pass3_kernel<<<dim3(NT, BB), 256>>>(w_t, b_t);
    final_kernel<<<dim3(32, BB), 256>>>(gamma, beta, out);
}

// round 17
// speedup vs baseline: 1.4217x; 1.4217x over previous
#include <cuda_runtime.h>
#include <cuda_fp16.h>

#define BB 4
#define NN 4096
#define DD 16
#define CC 128
#define LOG2E 1.4426950408889634f
#define NT 32

typedef unsigned long long ull;

__device__ __align__(16) float g_Q[BB * NN * DD];
__device__ __align__(16) __half g_Kh[BB * NN * DD];  // fp16 K, pre-scaled by log2(e)
__device__ __align__(16) float g_V[BB * NN * DD];    // after colsum: u = colinv * v
__device__ __align__(16) __half g_E[(size_t)BB * NN * NN];  // exp(e), M-MAJOR: [b][m][n]
__device__ float g_rowinv[BB * NN];
__device__ float g_T[BB * DD * NN];
__device__ float g_part[BB * NT * 8];

__device__ __forceinline__ ull pack2(float lo, float hi) {
    ull r; asm("mov.b64 %0, {%1, %2};" : "=l"(r) : "f"(lo), "f"(hi)); return r;
}
__device__ __forceinline__ ull fma2(ull a, ull b, ull c) {
    ull d; asm("fma.rn.f32x2 %0, %1, %2, %3;" : "=l"(d) : "l"(a), "l"(b), "l"(c)); return d;
}
__device__ __forceinline__ ull add2(ull a, ull b) {
    ull d; asm("add.rn.f32x2 %0, %1, %2;" : "=l"(d) : "l"(a), "l"(b)); return d;
}
__device__ __forceinline__ float ex2(float x) {
    float y; asm("ex2.approx.ftz.f32 %0, %1;" : "=f"(y) : "f"(x)); return y;
}
__device__ __forceinline__ unsigned h2u(__half2 h) {
    union { __half2 h; unsigned u; } cv; cv.h = h; return cv.u;
}
__device__ __forceinline__ void cpa16(unsigned dst, const void* src) {
    asm volatile("cp.async.ca.shared.global [%0], [%1], 16;" :: "r"(dst), "l"(src));
}
__device__ __forceinline__ void cp_commit() { asm volatile("cp.async.commit_group;"); }
template <int N> __device__ __forceinline__ void cp_wait() {
    asm volatile("cp.async.wait_group %0;" :: "n"(N));
}
__device__ __forceinline__ void ldk(ull* kk, const float* p) {
    const ulonglong2* k2 = (const ulonglong2*)p;
#pragma unroll
    for (int i = 0; i < 4; i++) { ulonglong2 t = k2[i]; kk[2 * i] = t.x; kk[2 * i + 1] = t.y; }
}

// mma.sync m16n8k16 row.col f32 = f16*f16 + f32
__device__ __forceinline__ void mma16816(float& d0, float& d1, float& d2, float& d3,
                                         unsigned a0, unsigned a1, unsigned a2, unsigned a3,
                                         unsigned b0, unsigned b1) {
    asm volatile(
        "mma.sync.aligned.m16n8k16.row.col.f32.f16.f16.f32 "
        "{%0,%1,%2,%3}, {%4,%5,%6,%7}, {%8,%9}, {%10,%11,%12,%13};"
        : "=f"(d0), "=f"(d1), "=f"(d2), "=f"(d3)
        : "r"(a0), "r"(a1), "r"(a2), "r"(a3), "r"(b0), "r"(b1),
          "f"(0.f), "f"(0.f), "f"(0.f), "f"(0.f));
}

// ---------------------------------------------------------------------------
// Kernel 1: projections. Q fp32; K fp16 pre-scaled by log2(e); V fp32.
// ---------------------------------------------------------------------------
__global__ void proj_kernel(const float* __restrict__ x_q, const float* __restrict__ x_kv,
                            const float* __restrict__ xyz_q, const float* __restrict__ xyz_kv,
                            const float* __restrict__ w_qk, const float* __restrict__ w_v,
                            const float* __restrict__ b_v,
                            const float* __restrict__ w_pos_q, const float* __restrict__ w_pos_kv) {
    __shared__ __align__(16) float s_wqk[CC][DD];
    __shared__ __align__(16) float s_wv[CC][DD];
    const int b = blockIdx.z;
    const int isKV = blockIdx.y;
    const int n = blockIdx.x * 128 + threadIdx.x;
    for (int i = threadIdx.x; i < CC * DD; i += 128) {
        int d = i / CC, c = i % CC;
        s_wqk[c][d] = w_qk[i];
        s_wv[c][d] = w_v[i];
    }
    __syncthreads();
    if (isKV == 0) {
        float p0 = xyz_q[(b * 3 + 0) * NN + n];
        float p1 = xyz_q[(b * 3 + 1) * NN + n];
        float p2 = xyz_q[(b * 3 + 2) * NN + n];
        float acc[DD];
#pragma unroll
        for (int d = 0; d < DD; d++)
            acc[d] = w_pos_q[d * 3] * p0 + w_pos_q[d * 3 + 1] * p1 + w_pos_q[d * 3 + 2] * p2;
        const float* xp = x_q + (size_t)b * CC * NN + n;
#pragma unroll 4
        for (int c = 0; c < CC; c++) {
            float xv = xp[(size_t)c * NN];
            const float4* w4 = (const float4*)s_wqk[c];
#pragma unroll
            for (int i = 0; i < 4; i++) {
                float4 w = w4[i];
                acc[4 * i + 0] += w.x * xv; acc[4 * i + 1] += w.y * xv;
                acc[4 * i + 2] += w.z * xv; acc[4 * i + 3] += w.w * xv;
            }
        }
        float4* qp = (float4*)(g_Q + ((size_t)(b * NN + n)) * DD);
#pragma unroll
        for (int i = 0; i < 4; i++)
            qp[i] = make_float4(acc[4 * i], acc[4 * i + 1], acc[4 * i + 2], acc[4 * i + 3]);
    } else {
        float p0 = xyz_kv[(b * 3 + 0) * NN + n];
        float p1 = xyz_kv[(b * 3 + 1) * NN + n];
        float p2 = xyz_kv[(b * 3 + 2) * NN + n];
        float ak[DD], av[DD];
#pragma unroll
        for (int d = 0; d < DD; d++) {
            float pos = w_pos_kv[d * 3] * p0 + w_pos_kv[d * 3 + 1] * p1 + w_pos_kv[d * 3 + 2] * p2;
            ak[d] = pos;
            av[d] = pos + b_v[d];
        }
        const float* xp = x_kv + (size_t)b * CC * NN + n;
#pragma unroll 2
        for (int c = 0; c < CC; c++) {
            float xv = xp[(size_t)c * NN];
            const float4* wq4 = (const float4*)s_wqk[c];
            const float4* wv4 = (const float4*)s_wv[c];
#pragma unroll
            for (int i = 0; i < 4; i++) {
                float4 wq = wq4[i], wv = wv4[i];
                ak[4 * i + 0] += wq.x * xv; ak[4 * i + 1] += wq.y * xv;
                ak[4 * i + 2] += wq.z * xv; ak[4 * i + 3] += wq.w * xv;
                av[4 * i + 0] += wv.x * xv; av[4 * i + 1] += wv.y * xv;
                av[4 * i + 2] += wv.z * xv; av[4 * i + 3] += wv.w * xv;
            }
        }
        union { __half2 h[8]; uint4 u[2]; } kh;
#pragma unroll
        for (int i = 0; i < 8; i++)
            kh.h[i] = __floats2half2_rn(ak[2 * i] * LOG2E, ak[2 * i + 1] * LOG2E);
        uint4* kp = (uint4*)(g_Kh + ((size_t)(b * NN + n)) * DD);
        kp[0] = kh.u[0];
        kp[1] = kh.u[1];
        float4* vp = (float4*)(g_V + ((size_t)(b * NN + n)) * DD);
#pragma unroll
        for (int i = 0; i < 4; i++)
            vp[i] = make_float4(av[4 * i], av[4 * i + 1], av[4 * i + 2], av[4 * i + 3]);
    }
}

// ---------------------------------------------------------------------------
// Kernel 2: rowsum via HMMA with swapped roles: A = K-tile (m-rows), B = Q
// (n-cols). D rows = m -> E stores are m-major, quad-contiguous along n.
// No smem, no barriers; warp owns 8 n-columns and sweeps all m.
// ---------------------------------------------------------------------------
__global__ __launch_bounds__(256) void rowsum_kernel() {
    const int tid = threadIdx.x, lane = tid & 31, w = tid >> 5;
    const int g = lane >> 2, t = lane & 3;
    const int b = blockIdx.y;
    const int nb = blockIdx.x * 64 + w * 8;   // warp's 8 n-columns

    // B fragment: Q row nb+g (fp32 -> fp16); b0 = d{2t,2t+1}, b1 = d{2t+8,2t+9}
    unsigned b0, b1;
    {
        const float2* qp = (const float2*)(g_Q + ((size_t)(b * NN + nb + g)) * DD);
        float2 qa = qp[t], qb = qp[t + 4];
        b0 = h2u(__floats2half2_rn(qa.x, qa.y));
        b1 = h2u(__floats2half2_rn(qb.x, qb.y));
    }

    const __half* kbase = g_Kh + (size_t)b * NN * DD;
    __half* ebase = g_E + (size_t)b * NN * NN;
    float acc0 = 0.f, acc1 = 0.f;

#pragma unroll 4
    for (int mt = 0; mt < 256; ++mt) {
        const int m0 = mt * 16;
        const __half* k0 = kbase + (size_t)(m0 + g) * DD;
        const __half* k1 = k0 + 8 * DD;
        unsigned a0 = *(const unsigned*)(k0 + 2 * t);
        unsigned a2 = *(const unsigned*)(k0 + 2 * t + 8);
        unsigned a1 = *(const unsigned*)(k1 + 2 * t);
        unsigned a3 = *(const unsigned*)(k1 + 2 * t + 8);
        float d0, d1, d2, d3;
        mma16816(d0, d1, d2, d3, a0, a1, a2, a3, b0, b1);
        // d0 = E(m0+g, nb+2t), d1 = (m0+g, nb+2t+1), d2/d3 = row m0+g+8
        float e0 = ex2(d0), e1 = ex2(d1), e2 = ex2(d2), e3 = ex2(d3);
        acc0 += e0 + e2;
        acc1 += e1 + e3;
        *(__half2*)(ebase + (size_t)(m0 + g) * NN + nb + 2 * t) = __floats2half2_rn(e0, e1);
        *(__half2*)(ebase + (size_t)(m0 + g + 8) * NN + nb + 2 * t) = __floats2half2_rn(e2, e3);
    }

    // reduce over g (lanes xor 4, 8, 16); result lands on g == 0 lanes
    acc0 += __shfl_xor_sync(0xffffffffu, acc0, 4);
    acc0 += __shfl_xor_sync(0xffffffffu, acc0, 8);
    acc0 += __shfl_xor_sync(0xffffffffu, acc0, 16);
    acc1 += __shfl_xor_sync(0xffffffffu, acc1, 4);
    acc1 += __shfl_xor_sync(0xffffffffu, acc1, 8);
    acc1 += __shfl_xor_sync(0xffffffffu, acc1, 16);
    if (g == 0) {
        g_rowinv[b * NN + nb + 2 * t] = 1.0f / acc0;
        g_rowinv[b * NN + nb + 2 * t + 1] = 1.0f / acc1;
    }
}

// ---------------------------------------------------------------------------
// Kernel 3 (R11): colsum, MLP-restructured; folds colinv into V in place.
// ---------------------------------------------------------------------------
__global__ __launch_bounds__(256, 2) void colsum_kernel() {
    __shared__ __align__(16) float sri[NN];
    const int tid = threadIdx.x, lane = tid & 31, w = tid >> 5;
    const int b = blockIdx.y;
    const int m = blockIdx.x * 8 + w;
    {
        const float4* src = (const float4*)(g_rowinv + b * NN);
        float4* dst = (float4*)sri;
        for (int i = tid; i < NN / 4; i += 256) dst[i] = src[i];
    }
    __syncthreads();
    const __half* ep = g_E + ((size_t)(b * NN + m)) * NN;
    float s0 = 0.f, s1 = 0.f;
#pragma unroll
    for (int h = 0; h < 2; h++) {
        uint4 raw[8];
#pragma unroll
        for (int c = 0; c < 4; c++) {
            int n = (h * 4 + c) * 512 + lane * 16;
            raw[2 * c] = *(const uint4*)(ep + n);
            raw[2 * c + 1] = *(const uint4*)(ep + n + 8);
        }
#pragma unroll
        for (int c = 0; c < 4; c++) {
            int n = (h * 4 + c) * 512 + lane * 16;
            const __half2* ha = (const __half2*)&raw[2 * c];
            const __half2* hb = (const __half2*)&raw[2 * c + 1];
            const float4* rp = (const float4*)(sri + n);
            float4 p0 = rp[0], p1 = rp[1], p2 = rp[2], p3 = rp[3];
            float2 f;
            f = __half22float2(ha[0]); s0 += f.x * p0.x + f.y * p0.y;
            f = __half22float2(ha[1]); s1 += f.x * p0.z + f.y * p0.w;
            f = __half22float2(ha[2]); s0 += f.x * p1.x + f.y * p1.y;
            f = __half22float2(ha[3]); s1 += f.x * p1.z + f.y * p1.w;
            f = __half22float2(hb[0]); s0 += f.x * p2.x + f.y * p2.y;
            f = __half22float2(hb[1]); s1 += f.x * p2.z + f.y * p2.w;
            f = __half22float2(hb[2]); s0 += f.x * p3.x + f.y * p3.y;
            f = __half22float2(hb[3]); s1 += f.x * p3.z + f.y * p3.w;
        }
    }
    float s = s0 + s1;
#pragma unroll
    for (int o = 16; o > 0; o >>= 1) s += __shfl_xor_sync(0xffffffffu, s, o);
    float ci = 1.0f / (1e-9f + s);
    if (lane < DD) {
        float* vp = g_V + ((size_t)(b * NN + m)) * DD + lane;
        *vp = *vp * ci;
    }
}

// ---------------------------------------------------------------------------
// Kernel 4 (R11): AV sweep. E reg double-buffer, u via cp.async.
// ---------------------------------------------------------------------------
__global__ __launch_bounds__(256, 1) void pass3_kernel(const float* __restrict__ w_t,
                                                       const float* __restrict__ b_t) {
    __shared__ __align__(16) float sbig[8192];
    __shared__ float swt[256];
    __shared__ float sred[1024];
    const int tid = threadIdx.x, lane = tid & 31, w = tid >> 5;
    const int b = blockIdx.y;
    const int n0blk = blockIdx.x * 128;

    swt[tid] = w_t[tid];

    const char* vbase = (const char*)(g_V + ((size_t)b * NN + (size_t)w * 512) * DD);
    const __half* ebase = g_E + ((size_t)(b * NN + w * 512)) * NN + n0blk + lane * 4;
    float* svw = sbig + w * 512;
    unsigned vb[2] = {(unsigned)__cvta_generic_to_shared(svw),
                      (unsigned)__cvta_generic_to_shared(svw + 256)};

    ull xr[32];
#pragma unroll
    for (int i = 0; i < 32; i++) xr[i] = 0ULL;

    auto issue = [&](int it, int buf) {
        const char* vsrc = vbase + (size_t)it * 1024;
        cpa16(vb[buf] + lane * 16, vsrc + lane * 16);
        cpa16(vb[buf] + 512 + lane * 16, vsrc + 512 + lane * 16);
        cp_commit();
    };
    auto ld_eh = [&](ull* eh, int it) {
        const __half* ep = ebase + (size_t)(it * 16) * NN;
#pragma unroll
        for (int j = 0; j < 16; j++) eh[j] = *(const ull*)(ep + (size_t)j * NN);
    };
    auto compute = [&](const ull* eh, int buf) {
        const float* vs = svw + buf * 256;
#pragma unroll
        for (int mm = 0; mm < 16; ++mm) {
            const __half2* hp = (const __half2*)&eh[mm];
            float2 wa = __half22float2(hp[0]);
            float2 wb = __half22float2(hp[1]);
            ull vv[8];
            ldk(vv, vs + mm * DD);
            ull w0 = pack2(wa.x, wa.x), w1 = pack2(wa.y, wa.y);
            ull w2 = pack2(wb.x, wb.x), w3 = pack2(wb.y, wb.y);
#pragma unroll
            for (int i = 0; i < 8; i++) {
                xr[i]      = fma2(w0, vv[i], xr[i]);
                xr[8 + i]  = fma2(w1, vv[i], xr[8 + i]);
                xr[16 + i] = fma2(w2, vv[i], xr[16 + i]);
                xr[24 + i] = fma2(w3, vv[i], xr[24 + i]);
            }
        }
    };

    ull ehA[16], ehB[16];
    issue(0, 0);
    issue(1, 1);
    ld_eh(ehA, 0);
    cp_wait<1>();
    __syncwarp();

#pragma unroll 1
    for (int it = 0; it < 32; it += 2) {
        ld_eh(ehB, it + 1);
        compute(ehA, 0);
        __syncwarp();
        if (it + 2 < 32) { issue(it + 2, 0); cp_wait<1>(); } else { cp_wait<0>(); }
        __syncwarp();
        if (it + 2 < 32) ld_eh(ehA, it + 2);
        compute(ehB, 1);
        __syncwarp();
        if (it + 3 < 32) { issue(it + 3, 1); cp_wait<1>(); } else { cp_wait<0>(); }
        __syncwarp();
    }

    __syncthreads();
    if (w >= 4) {
        ull* d = (ull*)(sbig + ((size_t)(w - 4) * 128 + lane * 4) * DD);
#pragma unroll
        for (int i = 0; i < 32; i++) d[i] = xr[i];
    }
    __syncthreads();
    if (w < 4) {
        ull* d = (ull*)(sbig + ((size_t)w * 128 + lane * 4) * DD);
#pragma unroll
        for (int i = 0; i < 32; i++) d[i] = add2(d[i], xr[i]);
    }
    __syncthreads();

    if (tid < 128) {
        const int row = n0blk + tid;
        float rinv = g_rowinv[b * NN + row];
        float xrf[DD];
        const float* s0 = sbig + tid * DD;
#pragma unroll
        for (int d = 0; d < DD; d++)
            xrf[d] = (s0[d] + s0[2048 + d] + s0[4096 + d] + s0[6144 + d]) * rinv;
        const float* qg = g_Q + ((size_t)(b * NN + row)) * DD;
        float diff[DD];
#pragma unroll
        for (int d = 0; d < DD; d++) diff[d] = qg[d] - xrf[d];
        float gs[4] = {0.f, 0.f, 0.f, 0.f}, gs2[4] = {0.f, 0.f, 0.f, 0.f};
#pragma unroll
        for (int o = 0; o < DD; o++) {
            float s = b_t[o];
#pragma unroll
            for (int d = 0; d < DD; d++) s += swt[o * DD + d] * diff[d];
            g_T[((size_t)(b * DD + o)) * NN + row] = s;
            gs[o >> 2] += s;
            gs2[o >> 2] += s * s;
        }
#pragma unroll
        for (int g = 0; g < 4; g++) {
            sred[tid * 8 + g] = gs[g];
            sred[tid * 8 + 4 + g] = gs2[g];
        }
    }
    __syncthreads();
    for (int s = 64; s > 0; s >>= 1) {
        if (tid < s) {
#pragma unroll
            for (int j = 0; j < 8; j++) sred[tid * 8 + j] += sred[(tid + s) * 8 + j];
        }
        __syncthreads();
    }
    if (tid < 8) g_part[((size_t)(b * NT + blockIdx.x)) * 8 + tid] = sred[tid];
}

// ---------------------------------------------------------------------------
// Kernel 5 (R11): finalize GN stats, relu, + q^T.
// ---------------------------------------------------------------------------
__global__ void final_kernel(const float* __restrict__ gamma, const float* __restrict__ beta,
                             float* __restrict__ out) {
    __shared__ float sq[128 * 17];
    __shared__ float ssc[DD], ssh[DD];
    const int b = blockIdx.y;
    const int tid = threadIdx.x;
    const int n0 = blockIdx.x * 128;
    if (tid < DD) {
        int g = tid >> 2;
        float s = 0.f, s2 = 0.f;
        for (int t = 0; t < NT; t++) {
            s += g_part[(b * NT + t) * 8 + g];
            s2 += g_part[(b * NT + t) * 8 + 4 + g];
        }
        float cnt = (float)(4 * NN);
        float mean = s / cnt;
        float var = s2 / cnt - mean * mean;
        float inv = rsqrtf(var + 1e-5f);
        float sc = gamma[tid] * inv;
        ssc[tid] = sc;
        ssh[tid] = beta[tid] - mean * sc;
    }
    const float* qsrc = g_Q + ((size_t)(b * NN + n0)) * DD;
    for (int i = tid; i < 128 * DD; i += 256) sq[(i >> 4) * 17 + (i & 15)] = qsrc[i];
    __syncthreads();
    for (int i = tid; i < 128 * DD; i += 256) {
        int c = i >> 7, j = i & 127;
        size_t idx = ((size_t)(b * DD + c)) * NN + n0 + j;
        float tv = g_T[idx];
        float r = fmaxf(tv * ssc[c] + ssh[c], 0.f);
        out[idx] = r + sq[j * 17 + c];
    }
}

extern "C" void kernel_launch(void* const* d_in, const int* in_sizes, int n_in,
                              void* d_out, int out_size) {
    const float* x_q      = (const float*)d_in[0];
    const float* x_kv     = (const float*)d_in[1];
    const float* xyz_q    = (const float*)d_in[2];
    const float* xyz_kv   = (const float*)d_in[3];
    const float* w_qk     = (const float*)d_in[4];
    const float* w_v      = (const float*)d_in[5];
    const float* b_v      = (const float*)d_in[6];
    const float* w_t      = (const float*)d_in[7];
    const float* b_t      = (const float*)d_in[8];
    const float* gamma    = (const float*)d_in[9];
    const float* beta     = (const float*)d_in[10];
    const float* w_pos_q  = (const float*)d_in[11];
    const float* w_pos_kv = (const float*)d_in[12];
    float* out = (float*)d_out;

    proj_kernel<<<dim3(32, 2, BB), 128>>>(x_q, x_kv, xyz_q, xyz_kv, w_qk, w_v, b_v,
                                          w_pos_q, w_pos_kv);
    rowsum_kernel<<<dim3(64, BB), 256>>>();
    colsum_kernel<<<dim3(512, BB), 256>>>();
    pass3_kernel<<<dim3(NT, BB), 256>>>(w_t, b_t);
    final_kernel<<<dim3(32, BB), 256>>>(gamma, beta, out);
}